// round 12
// baseline (speedup 1.0000x reference)
#include <cuda_runtime.h>
#include <math_constants.h>

#define NP    16384
#define GRIDD 32
#define NCELL (GRIDD * GRIDD * GRIDD)   // 32768
#define ORG   (-4.5f)
#define WID   (9.0f / GRIDD)            // 0.28125
#define INVW  (GRIDD / 9.0f)
#define FULLM 0xffffffffu
#define FXS   268435456.0f              // 2^28 fixed point
#define CAP   64
#define OVCAP 1024
#define NBLK  592                        // 4 blocks/SM x 148 SMs (resident by launch_bounds)
#define TPB   256
#define WTOT  (NBLK * (TPB / 32))        // 4736 warps

// ---------------- device scratch (zero-init; kernel self-resets for replays) ----
__device__ int    g_count[2][NCELL];
__device__ float4 g_bkt[2][NCELL * CAP];
__device__ float4 g_dense[2][NP];
__device__ int    g_ovf_n[2];
__device__ float4 g_ovf[2][OVCAP];
__device__ unsigned long long g_dist_acc;
__device__ unsigned long long g_col_acc;
__device__ unsigned g_bar_cnt;           // self-resetting
__device__ unsigned g_bar_gen;           // monotone across replays

__device__ __forceinline__ int clampi(int v, int lo, int hi) {
    return v < lo ? lo : (v > hi ? hi : v);
}
__device__ __forceinline__ void cell_of(float x, float y, float z,
                                        int& cx, int& cy, int& cz) {
    cx = clampi((int)floorf((x - ORG) * INVW), 0, GRIDD - 1);
    cy = clampi((int)floorf((y - ORG) * INVW), 0, GRIDD - 1);
    cz = clampi((int)floorf((z - ORG) * INVW), 0, GRIDD - 1);
}
__device__ __forceinline__ float warp_min(float v) {
#pragma unroll
    for (int s = 16; s > 0; s >>= 1)
        v = fminf(v, __shfl_xor_sync(FULLM, v, s));
    return v;
}

// sense-reversing grid barrier; generation counter is monotone so the barrier
// is reusable across graph replays without reinitialization.
__device__ __forceinline__ void grid_barrier() {
    __syncthreads();
    if (threadIdx.x == 0) {
        volatile unsigned* gen_p = &g_bar_gen;
        unsigned gen = *gen_p;
        __threadfence();                          // release prior writes
        if (atomicAdd(&g_bar_cnt, 1u) == NBLK - 1) {
            g_bar_cnt = 0;
            __threadfence();
            *gen_p = gen + 1;
        } else {
            while (*gen_p == gen) __nanosleep(64);
        }
        __threadfence();                          // acquire others' writes
    }
    __syncthreads();
}

// cooperative brute force for ONE query (all 32 lanes)
__device__ __forceinline__ float brute_one(const float4* __restrict__ dns,
                                           float qx, float qy, float qz, int lane) {
    float b0 = CUDART_INF_F, b1 = CUDART_INF_F, b2 = CUDART_INF_F, b3 = CUDART_INF_F;
#pragma unroll 8
    for (int p = lane; p < NP; p += 128) {
        float4 ga = dns[p];
        float4 gb = dns[p + 32];
        float4 gc = dns[p + 64];
        float4 gd = dns[p + 96];
        float dx, dy, dz;
        dx = qx - ga.x; dy = qy - ga.y; dz = qz - ga.z;
        b0 = fminf(b0, fmaf(dx, dx, fmaf(dy, dy, dz * dz)));
        dx = qx - gb.x; dy = qy - gb.y; dz = qz - gb.z;
        b1 = fminf(b1, fmaf(dx, dx, fmaf(dy, dy, dz * dz)));
        dx = qx - gc.x; dy = qy - gc.y; dz = qz - gc.z;
        b2 = fminf(b2, fmaf(dx, dx, fmaf(dy, dy, dz * dz)));
        dx = qx - gd.x; dy = qy - gd.y; dz = qz - gd.z;
        b3 = fminf(b3, fmaf(dx, dx, fmaf(dy, dy, dz * dz)));
    }
    return warp_min(fminf(fminf(b0, b1), fminf(b2, b3)));
}

// broadcast a batch of candidates (lane j holds candidate j, valid j < m)
__device__ __forceinline__ void proc_batch(
    float gx, float gy, float gz, int m, bool dual,
    float q1x, float q1y, float q1z,
    float q2x, float q2y, float q2z,
    float& b1, float& b2)
{
    if (!dual) {
#pragma unroll 4
        for (int j = 0; j < m; j++) {
            float bx = __shfl_sync(FULLM, gx, j);
            float by = __shfl_sync(FULLM, gy, j);
            float bz = __shfl_sync(FULLM, gz, j);
            float dx = q1x - bx, dy = q1y - by, dz = q1z - bz;
            b1 = fminf(b1, fmaf(dx, dx, fmaf(dy, dy, dz * dz)));
        }
    } else {
#pragma unroll 4
        for (int j = 0; j < m; j++) {
            float bx = __shfl_sync(FULLM, gx, j);
            float by = __shfl_sync(FULLM, gy, j);
            float bz = __shfl_sync(FULLM, gz, j);
            float dx = q1x - bx, dy = q1y - by, dz = q1z - bz;
            b1 = fminf(b1, fmaf(dx, dx, fmaf(dy, dy, dz * dz)));
            dx = q2x - bx; dy = q2y - by; dz = q2z - bz;
            b2 = fminf(b2, fmaf(dx, dx, fmaf(dy, dy, dz * dz)));
        }
    }
}

// process one cell's queries against its 27/125-cell neighborhood
__device__ void process_cell(int cl, int cell, int cnt, int lane) {
    const int sdb = cl ^ 1;
    const int nq = min(cnt, CAP);
    const bool dual = (nq > 32);
    const int cx = cell & 31, cy = (cell >> 5) & 31, cz = cell >> 10;

    const bool a1 = lane < nq;
    const bool a2 = lane + 32 < nq;
    float4 q1 = make_float4(0.f, 0.f, 0.f, 0.f), q2 = q1;
    if (a1) q1 = g_bkt[cl][cell * CAP + lane];
    if (a2) q2 = g_bkt[cl][cell * CAP + lane + 32];
    const bool qok1 = !a1 || (q1.x > ORG && q1.x < ORG + 9.0f &&
                              q1.y > ORG && q1.y < ORG + 9.0f &&
                              q1.z > ORG && q1.z < ORG + 9.0f);
    const bool qok2 = !a2 || (q2.x > ORG && q2.x < ORG + 9.0f &&
                              q2.y > ORG && q2.y < ORG + 9.0f &&
                              q2.z > ORG && q2.z < ORG + 9.0f);

    const int*    __restrict__ cnts = g_count[sdb];
    const float4* __restrict__ bkt  = g_bkt[sdb];

    float best1 = CUDART_INF_F, best2 = CUDART_INF_F;

    // opposite-cloud overflow points (normally none)
    int novf = min(g_ovf_n[sdb], OVCAP);
    for (int i0 = 0; i0 < novf; i0 += 32) {
        int i = i0 + lane;
        float gx = CUDART_INF_F, gy = 0.f, gz = 0.f;
        if (i < novf) { float4 g = g_ovf[sdb][i]; gx = g.x; gy = g.y; gz = g.z; }
        proc_batch(gx, gy, gz, min(32, novf - i0), dual,
                   q1.x, q1.y, q1.z, q2.x, q2.y, q2.z, best1, best2);
    }

    // -------- phase A: flattened 3x3x3, inline shfl addressing --------
    {
        int s = 0, c = 0;
        if (lane < 27) {
            int dz = lane / 9, rem = lane - dz * 9;
            int dy = rem / 3, dx = rem - dy * 3;
            int zc = cz + dz - 1, yc = cy + dy - 1, xc = cx + dx - 1;
            if ((unsigned)zc < GRIDD && (unsigned)yc < GRIDD && (unsigned)xc < GRIDD) {
                int cel = (zc * GRIDD + yc) * GRIDD + xc;
                c = min(cnts[cel], CAP);
                s = cel * CAP;
            }
        }
        int p = c;
#pragma unroll
        for (int d = 1; d < 32; d <<= 1) {
            int v = __shfl_up_sync(FULLM, p, d);
            if (lane >= d) p += v;
        }
        int E  = __shfl_sync(FULLM, p, 26);
        int pe = p - c;
        for (int i0 = 0; i0 < E; i0 += 32) {
            int i = i0 + lane;
            int addr = 0;
#pragma unroll
            for (int r = 0; r < 27; r++) {
                int Pr = __shfl_sync(FULLM, pe, r);
                int Sr = __shfl_sync(FULLM, s,  r);
                if (i >= Pr) addr = Sr + (i - Pr);
            }
            float gx = CUDART_INF_F, gy = 0.f, gz = 0.f;
            if (i < E) { float4 g = bkt[addr]; gx = g.x; gy = g.y; gz = g.z; }
            proc_batch(gx, gy, gz, min(32, E - i0), dual,
                       q1.x, q1.y, q1.z, q2.x, q2.y, q2.z, best1, best2);
        }
    }

    const float B1 = WID * WID;      // outside 3^3 box >= WID from this cell
    unsigned bad = __ballot_sync(FULLM,
        (a1 && (!qok1 || best1 > B1)) || (a2 && (!qok2 || best2 > B1)));

    if (bad) {
        // -------- phase B: flattened 5x5x5 (rare) --------
        for (int cb = 0; cb < 125; cb += 32) {
            int cc2 = cb + lane;
            int s2 = 0, c2 = 0;
            if (cc2 < 125) {
                int dz = cc2 / 25, rem = cc2 - dz * 25;
                int dy = rem / 5, dxx = rem - dy * 5;
                int zc = cz + dz - 2, yc = cy + dy - 2, xc = cx + dxx - 2;
                if ((unsigned)zc < GRIDD && (unsigned)yc < GRIDD && (unsigned)xc < GRIDD) {
                    int cel = (zc * GRIDD + yc) * GRIDD + xc;
                    c2 = min(cnts[cel], CAP);
                    s2 = cel * CAP;
                }
            }
            int p2 = c2;
#pragma unroll
            for (int d = 1; d < 32; d <<= 1) {
                int v = __shfl_up_sync(FULLM, p2, d);
                if (lane >= d) p2 += v;
            }
            int E2  = __shfl_sync(FULLM, p2, 31);
            int pe2 = p2 - c2;
            for (int i0 = 0; i0 < E2; i0 += 32) {
                int i = i0 + lane;
                int addr = 0;
#pragma unroll
                for (int r = 0; r < 32; r++) {
                    int Pr = __shfl_sync(FULLM, pe2, r);
                    int Sr = __shfl_sync(FULLM, s2,  r);
                    if (i >= Pr) addr = Sr + (i - Pr);
                }
                float gx = CUDART_INF_F, gy = 0.f, gz = 0.f;
                if (i < E2) { float4 g = bkt[addr]; gx = g.x; gy = g.y; gz = g.z; }
                proc_batch(gx, gy, gz, min(32, E2 - i0), dual,
                           q1.x, q1.y, q1.z, q2.x, q2.y, q2.z, best1, best2);
            }
        }

        // -------- phase C: per-query cooperative brute (rarer) --------
        const float B2 = 4.0f * WID * WID;
        const float4* __restrict__ dns = g_dense[sdb];
        unsigned f1 = __ballot_sync(FULLM, a1 && (!qok1 || best1 > B2));
        while (f1) {
            int r = __ffs(f1) - 1;
            f1 &= f1 - 1;
            float fx = __shfl_sync(FULLM, q1.x, r);
            float fy = __shfl_sync(FULLM, q1.y, r);
            float fz = __shfl_sync(FULLM, q1.z, r);
            float nb = brute_one(dns, fx, fy, fz, lane);
            if (lane == r) best1 = nb;
        }
        unsigned f2 = __ballot_sync(FULLM, a2 && (!qok2 || best2 > B2));
        while (f2) {
            int r = __ffs(f2) - 1;
            f2 &= f2 - 1;
            float fx = __shfl_sync(FULLM, q2.x, r);
            float fy = __shfl_sync(FULLM, q2.y, r);
            float fz = __shfl_sync(FULLM, q2.z, r);
            float nb = brute_one(dns, fx, fy, fz, lane);
            if (lane == r) best2 = nb;
        }
    }

    long long di = 0;
    if (a1) di += (long long)llrintf(sqrtf(best1) * FXS);
    if (a2) di += (long long)llrintf(sqrtf(best2) * FXS);
#pragma unroll
    for (int s = 16; s > 0; s >>= 1)
        di += __shfl_xor_sync(FULLM, di, s);
    if (lane == 0 && di != 0)
        atomicAdd(&g_dist_acc, (unsigned long long)di);
}

// ---------------- the ONE fused kernel ----------------
__global__ __launch_bounds__(TPB, 4)
void fused_kernel(const float* __restrict__ pred, const float* __restrict__ gt,
                  float* __restrict__ out) {
    const int gtid = blockIdx.x * TPB + threadIdx.x;
    const int lane = threadIdx.x & 31;
    const int gwarp = gtid >> 5;

    // ======== phase 1: bin + dense copy + color loss ========
    if (gtid < 2 * NP) {                         // warp-uniform (boundary at 16384)
        int cloud = gtid >> 14;
        int idx = gtid & (NP - 1);
        const float* r = (cloud ? gt : pred) + (size_t)idx * 6;
        float x = r[0], y = r[1], z = r[2];
        float4 pt = make_float4(x, y, z, 0.0f);
        g_dense[cloud][idx] = pt;

        int cx, cy, cz;
        cell_of(x, y, z, cx, cy, cz);
        int cell = (cz * GRIDD + cy) * GRIDD + cx;
        int slot = atomicAdd(&g_count[cloud][cell], 1);
        if (slot < CAP) {
            g_bkt[cloud][cell * CAP + slot] = pt;
        } else {
            int o = atomicAdd(&g_ovf_n[cloud], 1);
            if (o < OVCAP) g_ovf[cloud][o] = pt;
        }

        long long ci = 0;
        if (cloud == 0) {
            const float* pc = pred + (size_t)idx * 6;
            const float* gc = gt + (size_t)idx * 6;
            float col = fabsf(pc[3] - gc[3]) + fabsf(pc[4] - gc[4]) + fabsf(pc[5] - gc[5]);
            ci = llrintf(col * FXS);
        }
#pragma unroll
        for (int s = 16; s > 0; s >>= 1)
            ci += __shfl_xor_sync(FULLM, ci, s);
        if (lane == 0 && ci != 0)
            atomicAdd(&g_col_acc, (unsigned long long)ci);
    }

    grid_barrier();

    // ======== phase 2: NN queries, one warp per nonempty cell ========
    {
        // lane k preloads the count of this warp's k-th work item (1 round trip)
        int myitem = gwarp + lane * WTOT;
        int mycnt = 0;
        if (myitem < 2 * NCELL) mycnt = ((const int*)g_count)[myitem];
        unsigned act = __ballot_sync(FULLM, mycnt > 0);
        while (act) {
            int k = __ffs(act) - 1;
            act &= act - 1;
            int item = gwarp + k * WTOT;
            int cnt = __shfl_sync(FULLM, mycnt, k);
            process_cell(item >> 15, item & (NCELL - 1), cnt, lane);
        }
        // overflow queries (normally none)
        if (gwarp < 2) {
            int cl = gwarp;
            int n = min(g_ovf_n[cl], OVCAP);
            for (int o = 0; o < n; o++) {
                float4 q = g_ovf[cl][o];
                float nb = brute_one(g_dense[cl ^ 1], q.x, q.y, q.z, lane);
                if (lane == 0)
                    atomicAdd(&g_dist_acc,
                              (unsigned long long)(long long)llrintf(sqrtf(nb) * FXS));
            }
        }
    }

    grid_barrier();

    // ======== phase 3: combine + reset for next replay ========
    if (gtid == 0) {
        double dist = (double)(long long)g_dist_acc * (1.0 / 268435456.0);
        double col  = (double)(long long)g_col_acc  * (1.0 / 268435456.0);
        out[0] = (float)(dist / (double)NP + 0.1 * col / (double)(NP * 3));
        g_dist_acc = 0;
        g_col_acc  = 0;
    }
    if (gtid == 32) { g_ovf_n[0] = 0; g_ovf_n[1] = 0; }
    if (gtid < 2 * NCELL) ((int*)g_count)[gtid] = 0;
}

extern "C" void kernel_launch(void* const* d_in, const int* in_sizes, int n_in,
                              void* d_out, int out_size) {
    const float* pred = (const float*)d_in[0];
    const float* gt   = (const float*)d_in[1];
    float* out        = (float*)d_out;
    (void)in_sizes; (void)n_in; (void)out_size;

    fused_kernel<<<NBLK, TPB>>>(pred, gt, out);
}